// round 5
// baseline (speedup 1.0000x reference)
#include <cuda_runtime.h>
#include <math.h>

namespace {
constexpr int BS = 16, L = 2048, DIM = 512, G = 2, VD = 256, NC = 320;
constexpr float EPS = 1e-5f;
}

// ---------------- scratch (device globals; no allocation allowed) ----------
__device__ float g_MT[G][VD][NC];      // M^T[g][u][c] : dots = x @ MT
__device__ float g_S1[G][NC];
__device__ float g_S2[G][NC];
__device__ float g_e2[NC];
__device__ float g_Bc[BS][G][NC];
__device__ float g_Q[G][VD][VD];       // W^T W per group
__device__ float g_sW[G][VD];          // col-sums of W per group
__device__ float g_xs[BS * G][2][VD];  // per (b,g) per k-half row-sums of x
__device__ float g_C[BS * G][2][6][64 * 128]; // Gram tiles [v][u], 12.6MB

// ---------------- packed f32x2 helpers (Blackwell FFMA2 pipe) --------------
__device__ __forceinline__ unsigned long long pk2(float lo, float hi) {
    unsigned long long r;
    asm("mov.b64 %0, {%1, %2};" : "=l"(r) : "f"(lo), "f"(hi));
    return r;
}
__device__ __forceinline__ void upk2(unsigned long long v, float &lo, float &hi) {
    asm("mov.b64 {%0, %1}, %2;" : "=f"(lo), "=f"(hi) : "l"(v));
}
__device__ __forceinline__ unsigned long long ffma2(unsigned long long a,
                                                    unsigned long long b,
                                                    unsigned long long c) {
    unsigned long long d;
    asm("fma.rn.f32x2 %0, %1, %2, %3;" : "=l"(d) : "l"(a), "l"(b), "l"(c));
    return d;
}

// ---------------- cp.async helpers -----------------------------------------
__device__ __forceinline__ unsigned smem_u32(const void* p) {
    return (unsigned)__cvta_generic_to_shared(p);
}
__device__ __forceinline__ void cp_async16(unsigned dst, const void* src) {
    asm volatile("cp.async.cg.shared.global [%0], [%1], 16;\n" :: "r"(dst), "l"(src));
}
__device__ __forceinline__ void cp_commit() {
    asm volatile("cp.async.commit_group;\n");
}
__device__ __forceinline__ void cp_wait0() {
    asm volatile("cp.async.wait_group 0;\n" ::: "memory");
}

// ---------------- K0: fold W, gn_weight, emb into M^T; S1/S2/e2 ------------
__global__ void k0_prep(const float* __restrict__ W,
                        const float* __restrict__ gw,
                        const float* __restrict__ gb,
                        const float* __restrict__ emb) {
    const int c0 = blockIdx.x * 8, g = blockIdx.y, tid = threadIdx.x;
    __shared__ float es[8][VD];   // gw-scaled emb rows

    for (int idx = tid; idx < 8 * VD; idx += 256) {
        const int c = idx >> 8, o = idx & 255;
        es[c][o] = emb[(size_t)(c0 + c) * VD + o] * gw[g * VD + o];
    }
    __syncthreads();

    // reductions: warp w owns code c0+w
    const int w = tid >> 5, lane = tid & 31;
    {
        float s1 = 0.f, s2 = 0.f, s3 = 0.f;
        const float* ec = emb + (size_t)(c0 + w) * VD;
        for (int o = lane; o < VD; o += 32) {
            const float e = ec[o];
            s1 = fmaf(e, gw[g * VD + o], s1);
            s2 = fmaf(e, gb[g * VD + o], s2);
            s3 = fmaf(e, e, s3);
        }
        const unsigned FULL = 0xffffffffu;
#pragma unroll
        for (int off = 16; off; off >>= 1) {
            s1 += __shfl_xor_sync(FULL, s1, off);
            s2 += __shfl_xor_sync(FULL, s2, off);
            s3 += __shfl_xor_sync(FULL, s3, off);
        }
        if (lane == 0) {
            g_S1[g][c0 + w] = s1;
            g_S2[g][c0 + w] = s2;
            if (g == 0) g_e2[c0 + w] = s3;
        }
    }

    float acc[8];
#pragma unroll
    for (int c = 0; c < 8; ++c) acc[c] = 0.f;
    const float* Wg = W + (size_t)g * VD * VD + tid;
#pragma unroll 4
    for (int o = 0; o < VD; ++o) {
        const float wv = Wg[(size_t)o * VD];
#pragma unroll
        for (int c = 0; c < 8; ++c) acc[c] = fmaf(wv, es[c][o], acc[c]);
    }
    float4* dst = (float4*)&g_MT[g][tid][c0];
    dst[0] = make_float4(acc[0], acc[1], acc[2], acc[3]);
    dst[1] = make_float4(acc[4], acc[5], acc[6], acc[7]);
}

// ---------------- K0b: Q = W^T W per g; s_W col-sums ------------------------
// grid (4,4,G), 64x64 tiles, K=256 over o, scalar fmaf (tiny kernel).
__global__ void k0b_gram(const float* __restrict__ W) {
    const int g = blockIdx.z, bi = blockIdx.y, bj = blockIdx.x;
    const int tid = threadIdx.x, tx = tid & 15, ty = tid >> 4;
    __shared__ float As[16][64];
    __shared__ float Bs[16][64];
    const float* Wg = W + (size_t)g * VD * VD;

    float acc[4][4];
#pragma unroll
    for (int i = 0; i < 4; ++i)
#pragma unroll
        for (int j = 0; j < 4; ++j) acc[i][j] = 0.f;

    const int okk = tid >> 4, u4 = (tid & 15) * 4;
    float sw = 0.f;
    const bool diag = (bi == bj);

    for (int oc = 0; oc < VD; oc += 16) {
        __syncthreads();
        *(float4*)&As[okk][u4] = *(const float4*)(Wg + (size_t)(oc + okk) * VD + bi * 64 + u4);
        *(float4*)&Bs[okk][u4] = *(const float4*)(Wg + (size_t)(oc + okk) * VD + bj * 64 + u4);
        __syncthreads();
#pragma unroll
        for (int kk = 0; kk < 16; ++kk) {
            const float4 a = *(const float4*)&As[kk][ty * 4];
            const float4 bq = *(const float4*)&Bs[kk][tx * 4];
            const float av[4] = { a.x, a.y, a.z, a.w };
            const float bv[4] = { bq.x, bq.y, bq.z, bq.w };
#pragma unroll
            for (int i = 0; i < 4; ++i)
#pragma unroll
                for (int j = 0; j < 4; ++j) acc[i][j] = fmaf(av[i], bv[j], acc[i][j]);
        }
        if (diag && tid < 64) {
#pragma unroll
            for (int kk = 0; kk < 16; ++kk) sw += As[kk][tid];
        }
    }
#pragma unroll
    for (int i = 0; i < 4; ++i) {
        const int u = bi * 64 + ty * 4 + i;
        *(float4*)&g_Q[g][u][bj * 64 + tx * 4] =
            make_float4(acc[i][0], acc[i][1], acc[i][2], acc[i][3]);
    }
    if (diag && tid < 64) g_sW[g][bi * 64 + tid] = sw;
}

// ---------------- K1: SYRK  C = sum_l x x^T (lower tiles) + row-sums -------
// grid (6 tiles, 2 k-halves, 32 bg). 128x64 tiles, K=1024, double-buffered.
// tiles t: (ri,cj) in {(0,0),(0,1),(1,0),(1,1),(1,2),(1,3)}.
__global__ __launch_bounds__(256, 2) void k1_syrk(const float* __restrict__ x) {
    const int bg = blockIdx.z;
    const int b = bg >> 1, g = bg & 1;
    const int kh = blockIdx.y;
    const int t = blockIdx.x;
    const int ri = (t >= 2) ? 1 : 0;
    const int cj = (t < 2) ? t : (t - 2);
    const int tid = threadIdx.x, tx = tid & 15, ty = tid >> 4;

    __shared__ __align__(16) float As[2][8][128];    // natural rows (u)
    __shared__ __align__(16) float Bs2[2][8][128];   // duplicated cols (v,v)

    const size_t base = ((size_t)(b * L) + (size_t)kh * 1024) * DIM + g * VD;
    const float* Arow = x + base + ri * 128;
    const float* Brow = x + base + cj * 64;

    const int akk = tid >> 5, au4 = (tid & 31) * 4;
    const int bkk = tid >> 4, bv4 = (tid & 15) * 4;

    unsigned long long acc[4][4];
#pragma unroll
    for (int i = 0; i < 4; ++i)
#pragma unroll
        for (int j = 0; j < 4; ++j) acc[i][j] = 0ull;

    // prologue: chunk 0
    {
        const float4 av = *(const float4*)(Arow + (size_t)akk * DIM + au4);
        *(float4*)&As[0][akk][au4] = av;
        if (tid < 128) {
            const float4 bv = *(const float4*)(Brow + (size_t)bkk * DIM + bv4);
            Bs2[0][bkk][2 * bv4 + 0] = bv.x; Bs2[0][bkk][2 * bv4 + 1] = bv.x;
            Bs2[0][bkk][2 * bv4 + 2] = bv.y; Bs2[0][bkk][2 * bv4 + 3] = bv.y;
            Bs2[0][bkk][2 * bv4 + 4] = bv.z; Bs2[0][bkk][2 * bv4 + 5] = bv.z;
            Bs2[0][bkk][2 * bv4 + 6] = bv.w; Bs2[0][bkk][2 * bv4 + 7] = bv.w;
        }
    }
    __syncthreads();

    const bool diag = (t == 0) || (t == 4);   // cover u 0-127 / 128-255
    float xsum = 0.f;

    int s = 0;
    for (int kc = 0; kc < 128; ++kc) {
        float4 av, bv;
        const bool pf = kc < 127;
        if (pf) {
            const size_t l8 = (size_t)(kc + 1) * 8;
            av = *(const float4*)(Arow + (l8 + akk) * DIM + au4);
            if (tid < 128) bv = *(const float4*)(Brow + (l8 + bkk) * DIM + bv4);
        }
#pragma unroll
        for (int kk = 0; kk < 8; ++kk) {
            unsigned long long a[4], bb[4];
#pragma unroll
            for (int i = 0; i < 4; ++i)
                a[i] = *(const unsigned long long*)&As[s][kk][2 * ty + 32 * i];
#pragma unroll
            for (int j = 0; j < 4; ++j)
                bb[j] = *(const unsigned long long*)&Bs2[s][kk][2 * tx + 32 * j];
#pragma unroll
            for (int i = 0; i < 4; ++i)
#pragma unroll
                for (int j = 0; j < 4; ++j) acc[i][j] = ffma2(a[i], bb[j], acc[i][j]);
        }
        if (diag && tid < 128) {
#pragma unroll
            for (int kk = 0; kk < 8; ++kk) xsum += As[s][kk][tid];
        }
        if (pf) {
            const int d = s ^ 1;
            *(float4*)&As[d][akk][au4] = av;
            if (tid < 128) {
                Bs2[d][bkk][2 * bv4 + 0] = bv.x; Bs2[d][bkk][2 * bv4 + 1] = bv.x;
                Bs2[d][bkk][2 * bv4 + 2] = bv.y; Bs2[d][bkk][2 * bv4 + 3] = bv.y;
                Bs2[d][bkk][2 * bv4 + 4] = bv.z; Bs2[d][bkk][2 * bv4 + 5] = bv.z;
                Bs2[d][bkk][2 * bv4 + 6] = bv.w; Bs2[d][bkk][2 * bv4 + 7] = bv.w;
            }
        }
        __syncthreads();
        s ^= 1;
    }

    // store C tile, layout [v(64)][u(128)]
    float* Ct = &g_C[bg][kh][t][0];
#pragma unroll
    for (int i = 0; i < 4; ++i)
#pragma unroll
        for (int j = 0; j < 4; ++j) {
            float2 val;
            upk2(acc[i][j], val.x, val.y);
            const int e = (tx + 16 * j) * 128 + (2 * ty + 32 * i);
            *(float2*)&Ct[e] = val;
        }
    if (diag && tid < 128) g_xs[bg][kh][ri * 128 + tid] = xsum;
}

// ---------------- K2: mean/var from Gram -> per-code bias Bc ---------------
__global__ void k2_finalize() {   // grid 32 (bg), 256 threads
    const int bg = blockIdx.x, b = bg >> 1, g = bg & 1;
    const int tid = threadIdx.x;

    float lsum = g_sW[g][tid] * (g_xs[bg][0][tid] + g_xs[bg][1][tid]);
    float lss = 0.f;
    const float* Qg = &g_Q[g][0][0];
#pragma unroll
    for (int t = 0; t < 6; ++t) {
        const int ri = (t >= 2) ? 1 : 0;
        const int cj = (t < 2) ? t : (t - 2);
        const float* C0 = &g_C[bg][0][t][0];
        const float* C1 = &g_C[bg][1][t][0];
        for (int e = tid; e < 64 * 128; e += 256) {
            const int v = e >> 7, u = e & 127;
            const int ug = ri * 128 + u, vg = cj * 64 + v;
            if (ug < vg) continue;
            const float wgt = (ug == vg) ? 1.f : 2.f;
            lss = fmaf(wgt * Qg[(size_t)ug * VD + vg], C0[e] + C1[e], lss);
        }
    }
    const unsigned FULL = 0xffffffffu;
#pragma unroll
    for (int off = 16; off; off >>= 1) {
        lsum += __shfl_xor_sync(FULL, lsum, off);
        lss  += __shfl_xor_sync(FULL, lss, off);
    }
    __shared__ float sred[2][8];
    __shared__ float s_mean, s_sd;
    const int w = tid >> 5, lane = tid & 31;
    if (lane == 0) { sred[0][w] = lsum; sred[1][w] = lss; }
    __syncthreads();
    if (tid == 0) {
        float su = 0.f, ss = 0.f;
#pragma unroll
        for (int i = 0; i < 8; ++i) { su += sred[0][i]; ss += sred[1][i]; }
        const float invN = 1.f / (float)(VD * L);
        const float mean = su * invN;
        const float var = ss * invN - mean * mean;
        s_mean = mean;
        s_sd = sqrtf(var + EPS);
    }
    __syncthreads();
    for (int c = tid; c < NC; c += 256)
        g_Bc[b][g][c] = s_mean * g_S1[g][c] + (0.5f * g_e2[c] - g_S2[g][c]) * s_sd;
}

// ---------------- K3: dots = X @ M^T, argmax, gather codes -----------------
// 64 tokens x 320 codes / block; As stored DUPLICATED (a,a) -> no inner pk2.
__global__ __launch_bounds__(256, 2) void k3_vq(const float* __restrict__ x,
                                                const float* __restrict__ emb,
                                                float* __restrict__ out) {
    const int b = blockIdx.z, g = blockIdx.y, l0 = blockIdx.x * 64;
    const int tid = threadIdx.x, w = tid >> 5, lane = tid & 31;

    __shared__ __align__(16) float Ms[2][16][NC];    // 2 x 20 KB
    __shared__ __align__(16) float As2[2][16][130];  // duplicated tokens

    const float* xrow = x + ((size_t)(b * L + l0)) * DIM + g * VD;
    const float* Mg = &g_MT[g][0][0];

    const int la = tid >> 2;            // token this thread loads (0..63)
    const int qa = tid & 3;             // k-quad

    unsigned long long acc[8][5];
#pragma unroll
    for (int i = 0; i < 8; ++i)
#pragma unroll
        for (int j = 0; j < 5; ++j) acc[i][j] = 0ull;

    // prologue: chunk 0
#pragma unroll
    for (int n = 0; n < 5; ++n) {
        const int idx = tid + n * 256;
        const int r = idx / 80, col = (idx % 80) * 4;
        cp_async16(smem_u32(&Ms[0][r][col]), Mg + (size_t)r * NC + col);
    }
    cp_commit();
    {
        const float4 v = *(const float4*)(xrow + (size_t)la * DIM + qa * 4);
        *(unsigned long long*)&As2[0][qa * 4 + 0][2 * la] = pk2(v.x, v.x);
        *(unsigned long long*)&As2[0][qa * 4 + 1][2 * la] = pk2(v.y, v.y);
        *(unsigned long long*)&As2[0][qa * 4 + 2][2 * la] = pk2(v.z, v.z);
        *(unsigned long long*)&As2[0][qa * 4 + 3][2 * la] = pk2(v.w, v.w);
    }
    cp_wait0();
    __syncthreads();

    int s = 0;
    for (int step = 0; step < 16; ++step) {
        float4 an;
        if (step < 15) {
            const int kb = (step + 1) * 16;
#pragma unroll
            for (int n = 0; n < 5; ++n) {
                const int idx = tid + n * 256;
                const int r = idx / 80, col = (idx % 80) * 4;
                cp_async16(smem_u32(&Ms[s ^ 1][r][col]),
                           Mg + (size_t)(kb + r) * NC + col);
            }
            cp_commit();
            an = *(const float4*)(xrow + (size_t)la * DIM + kb + qa * 4);
        }
#pragma unroll
        for (int k = 0; k < 16; ++k) {
            unsigned long long m[5];
#pragma unroll
            for (int j = 0; j < 5; ++j)
                m[j] = *(const unsigned long long*)&Ms[s][k][j * 64 + lane * 2];
#pragma unroll
            for (int i = 0; i < 8; ++i) {
                const unsigned long long ad =
                    *(const unsigned long long*)&As2[s][k][2 * (w * 8 + i)];
#pragma unroll
                for (int j = 0; j < 5; ++j) acc[i][j] = ffma2(ad, m[j], acc[i][j]);
            }
        }
        if (step < 15) {
            const int d = s ^ 1;
            *(unsigned long long*)&As2[d][qa * 4 + 0][2 * la] = pk2(an.x, an.x);
            *(unsigned long long*)&As2[d][qa * 4 + 1][2 * la] = pk2(an.y, an.y);
            *(unsigned long long*)&As2[d][qa * 4 + 2][2 * la] = pk2(an.z, an.z);
            *(unsigned long long*)&As2[d][qa * 4 + 3][2 * la] = pk2(an.w, an.w);
        }
        cp_wait0();
        __syncthreads();
        s ^= 1;
    }

    // bias + argmax (tie-break: lowest code index)
    float2 bc[5];
#pragma unroll
    for (int j = 0; j < 5; ++j)
        bc[j] = *(const float2*)&g_Bc[b][g][j * 64 + lane * 2];

    const unsigned FULL = 0xffffffffu;
    int bestc[8];
#pragma unroll
    for (int i = 0; i < 8; ++i) {
        float bv = -1e30f; int bi = 0x7fffffff;
#pragma unroll
        for (int j = 0; j < 5; ++j) {
            float lo, hi; upk2(acc[i][j], lo, hi);
            const int c0 = j * 64 + lane * 2;
            const float s0 = lo - bc[j].x;
            const float s1 = hi - bc[j].y;
            if (s0 > bv || (s0 == bv && c0 < bi)) { bv = s0; bi = c0; }
            if (s1 > bv || (s1 == bv && (c0 + 1) < bi)) { bv = s1; bi = c0 + 1; }
        }
#pragma unroll
        for (int off = 16; off; off >>= 1) {
            const float ov = __shfl_xor_sync(FULL, bv, off);
            const int oc = __shfl_xor_sync(FULL, bi, off);
            if (ov > bv || (ov == bv && oc < bi)) { bv = ov; bi = oc; }
        }
        bestc[i] = bi;
    }

    // gather: out[b, l, g*VD : (g+1)*VD] = emb[bestc]
    float* orow = out + ((size_t)(b * L + l0 + w * 8)) * DIM + g * VD;
#pragma unroll
    for (int i = 0; i < 8; ++i) {
        const float4* src = (const float4*)(emb + (size_t)bestc[i] * VD);
        float4* dst = (float4*)(orow + (size_t)i * DIM);
        dst[lane] = src[lane];
        dst[lane + 32] = src[lane + 32];
    }
}

// ---------------- launch ---------------------------------------------------
extern "C" void kernel_launch(void* const* d_in, const int* in_sizes, int n_in,
                              void* d_out, int out_size) {
    (void)in_sizes; (void)n_in; (void)out_size;
    const float* x   = (const float*)d_in[0];
    const float* W   = (const float*)d_in[1];
    const float* gw  = (const float*)d_in[2];
    const float* gb  = (const float*)d_in[3];
    const float* emb = (const float*)d_in[4];
    float* out = (float*)d_out;

    k0_prep<<<dim3(NC / 8, G), 256>>>(W, gw, gb, emb);
    k0b_gram<<<dim3(4, 4, G), 256>>>(W);
    k1_syrk<<<dim3(6, 2, BS * G / 16 * 16 / 32 * 32 ? 32 : 32), 256>>>(x);
    k2_finalize<<<32, 256>>>();
    k3_vq<<<dim3(L / 64, G, BS), 256>>>(x, emb, out);
}

// round 8
// speedup vs baseline: 1.0905x; 1.0905x over previous
#include <cuda_runtime.h>
#include <math.h>

namespace {
constexpr int BS = 16, L = 2048, DIM = 512, G = 2, VD = 256, NC = 320;
constexpr float EPS = 1e-5f;
}

// ---------------- scratch (device globals; no allocation allowed) ----------
__device__ float g_MT[G][VD][NC];      // M^T[g][u][c] : dots = x @ MT
__device__ float g_S1[G][NC];
__device__ float g_S2[G][NC];
__device__ float g_e2[NC];
__device__ float g_part[BS][G][32][2]; // per-block partial {sum,sumsq}
__device__ float g_Bc[BS][G][NC];

// ---------------- packed f32x2 helpers (Blackwell FFMA2 pipe) --------------
__device__ __forceinline__ unsigned long long pk2(float lo, float hi) {
    unsigned long long r;
    asm("mov.b64 %0, {%1, %2};" : "=l"(r) : "f"(lo), "f"(hi));
    return r;
}
__device__ __forceinline__ void upk2(unsigned long long v, float &lo, float &hi) {
    asm("mov.b64 {%0, %1}, %2;" : "=f"(lo), "=f"(hi) : "l"(v));
}
__device__ __forceinline__ unsigned long long ffma2(unsigned long long a,
                                                    unsigned long long b,
                                                    unsigned long long c) {
    unsigned long long d;
    asm("fma.rn.f32x2 %0, %1, %2, %3;" : "=l"(d) : "l"(a), "l"(b), "l"(c));
    return d;
}

// ---------------- cp.async helpers -----------------------------------------
__device__ __forceinline__ unsigned smem_u32(const void* p) {
    return (unsigned)__cvta_generic_to_shared(p);
}
__device__ __forceinline__ void cp_async16(unsigned dst, const void* src) {
    asm volatile("cp.async.cg.shared.global [%0], [%1], 16;\n" :: "r"(dst), "l"(src));
}
__device__ __forceinline__ void cp_commit() {
    asm volatile("cp.async.commit_group;\n");
}
__device__ __forceinline__ void cp_wait0() {
    asm volatile("cp.async.wait_group 0;\n" ::: "memory");
}

// ---------------- K0: fold W, gn_weight, emb into M^T; S1/S2/e2 ------------
__global__ void k0_prep(const float* __restrict__ W,
                        const float* __restrict__ gw,
                        const float* __restrict__ gb,
                        const float* __restrict__ emb) {
    const int c0 = blockIdx.x * 8, g = blockIdx.y, tid = threadIdx.x;
    __shared__ float es[8][VD];   // gw-scaled emb rows

    for (int idx = tid; idx < 8 * VD; idx += 256) {
        const int c = idx >> 8, o = idx & 255;
        es[c][o] = emb[(size_t)(c0 + c) * VD + o] * gw[g * VD + o];
    }
    __syncthreads();

    // reductions: warp w owns code c0+w
    const int w = tid >> 5, lane = tid & 31;
    {
        float s1 = 0.f, s2 = 0.f, s3 = 0.f;
        const float* ec = emb + (size_t)(c0 + w) * VD;
        for (int o = lane; o < VD; o += 32) {
            const float e = ec[o];
            s1 = fmaf(e, gw[g * VD + o], s1);
            s2 = fmaf(e, gb[g * VD + o], s2);
            s3 = fmaf(e, e, s3);
        }
        const unsigned FULL = 0xffffffffu;
#pragma unroll
        for (int off = 16; off; off >>= 1) {
            s1 += __shfl_xor_sync(FULL, s1, off);
            s2 += __shfl_xor_sync(FULL, s2, off);
            s3 += __shfl_xor_sync(FULL, s3, off);
        }
        if (lane == 0) {
            g_S1[g][c0 + w] = s1;
            g_S2[g][c0 + w] = s2;
            if (g == 0) g_e2[c0 + w] = s3;
        }
    }

    float acc[8];
#pragma unroll
    for (int c = 0; c < 8; ++c) acc[c] = 0.f;
    const float* Wg = W + (size_t)g * VD * VD + tid;
#pragma unroll 4
    for (int o = 0; o < VD; ++o) {
        const float wv = Wg[(size_t)o * VD];
#pragma unroll
        for (int c = 0; c < 8; ++c) acc[c] = fmaf(wv, es[c][o], acc[c]);
    }
    float4* dst = (float4*)&g_MT[g][tid][c0];
    dst[0] = make_float4(acc[0], acc[1], acc[2], acc[3]);
    dst[1] = make_float4(acc[4], acc[5], acc[6], acc[7]);
}

// ---------------- K1: ze = X_g @ W_g^T, accumulate sum/sumsq ---------------
// 128x128 tile, K-chunks of 8, double-buffered; Bs stored DUPLICATED (b,b)
// so the inner loop is pure LDS.64 + ffma2 (no pk2).
__global__ __launch_bounds__(256, 2) void k1_stats(const float* __restrict__ x,
                                                   const float* __restrict__ W) {
    const int b = blockIdx.z >> 1, g = blockIdx.z & 1;
    const int l0 = blockIdx.y * 128, o0 = blockIdx.x * 128;
    const int tid = threadIdx.x;

    __shared__ __align__(16) float As[2][8][128];    // [k][l]
    __shared__ __align__(16) float Bs2[2][8][256];   // [k][2o] duplicated

    const float* Ag = x + ((size_t)(b * L + l0)) * DIM + g * VD;
    const float* Bg = W + (size_t)g * VD * VD + (size_t)o0 * VD;

    const int arow = tid >> 1;          // token row (and o row) this thread loads
    const int acol = (tid & 1) * 4;     // k offset
    const int tl = (tid >> 4) * 8;      // 8 tokens owned (pairs)
    const int om = tid & 15;            // o = om + 16*j (interleaved)

    unsigned long long acc[4][8];
#pragma unroll
    for (int i = 0; i < 4; ++i)
#pragma unroll
        for (int j = 0; j < 8; ++j) acc[i][j] = 0ull;

    // prologue: chunk 0
    {
        const float4 av = *(const float4*)(Ag + (size_t)arow * DIM + acol);
        const float4 bv = *(const float4*)(Bg + (size_t)arow * VD + acol);
        As[0][acol + 0][arow] = av.x; As[0][acol + 1][arow] = av.y;
        As[0][acol + 2][arow] = av.z; As[0][acol + 3][arow] = av.w;
        *(unsigned long long*)&Bs2[0][acol + 0][2 * arow] = pk2(bv.x, bv.x);
        *(unsigned long long*)&Bs2[0][acol + 1][2 * arow] = pk2(bv.y, bv.y);
        *(unsigned long long*)&Bs2[0][acol + 2][2 * arow] = pk2(bv.z, bv.z);
        *(unsigned long long*)&Bs2[0][acol + 3][2 * arow] = pk2(bv.w, bv.w);
    }
    __syncthreads();

    int s = 0;
    for (int kc = 0; kc < 32; ++kc) {
        float4 an, bn;
        if (kc < 31) {
            const int kb = (kc + 1) * 8;
            an = *(const float4*)(Ag + (size_t)arow * DIM + kb + acol);
            bn = *(const float4*)(Bg + (size_t)arow * VD + kb + acol);
        }
#pragma unroll
        for (int k = 0; k < 8; ++k) {
            unsigned long long ap[4], bb[8];
#pragma unroll
            for (int i = 0; i < 4; ++i)
                ap[i] = *(const unsigned long long*)&As[s][k][tl + 2 * i];
#pragma unroll
            for (int j = 0; j < 8; ++j)
                bb[j] = *(const unsigned long long*)&Bs2[s][k][2 * om + 32 * j];
#pragma unroll
            for (int j = 0; j < 8; ++j)
#pragma unroll
                for (int i = 0; i < 4; ++i) acc[i][j] = ffma2(ap[i], bb[j], acc[i][j]);
        }
        if (kc < 31) {
            const int d = s ^ 1;
            As[d][acol + 0][arow] = an.x; As[d][acol + 1][arow] = an.y;
            As[d][acol + 2][arow] = an.z; As[d][acol + 3][arow] = an.w;
            *(unsigned long long*)&Bs2[d][acol + 0][2 * arow] = pk2(bn.x, bn.x);
            *(unsigned long long*)&Bs2[d][acol + 1][2 * arow] = pk2(bn.y, bn.y);
            *(unsigned long long*)&Bs2[d][acol + 2][2 * arow] = pk2(bn.z, bn.z);
            *(unsigned long long*)&Bs2[d][acol + 3][2 * arow] = pk2(bn.w, bn.w);
        }
        __syncthreads();
        s ^= 1;
    }

    // local sum / sumsq over this thread's 64 outputs
    float ts = 0.f, tss = 0.f;
#pragma unroll
    for (int i = 0; i < 4; ++i)
#pragma unroll
        for (int j = 0; j < 8; ++j) {
            float lo, hi; upk2(acc[i][j], lo, hi);
            ts += lo + hi;
            tss = fmaf(lo, lo, tss); tss = fmaf(hi, hi, tss);
        }
    const unsigned FULL = 0xffffffffu;
#pragma unroll
    for (int off = 16; off; off >>= 1) {
        ts  += __shfl_xor_sync(FULL, ts, off);
        tss += __shfl_xor_sync(FULL, tss, off);
    }
    __shared__ float sred[2][8];
    const int w = tid >> 5, lane = tid & 31;
    if (lane == 0) { sred[0][w] = ts; sred[1][w] = tss; }
    __syncthreads();
    if (tid == 0) {
        float su = 0.f, ss = 0.f;
#pragma unroll
        for (int i = 0; i < 8; ++i) { su += sred[0][i]; ss += sred[1][i]; }
        const int slot = blockIdx.y * 2 + blockIdx.x;
        g_part[b][g][slot][0] = su;
        g_part[b][g][slot][1] = ss;
    }
}

// ---------------- K2: finalize mean/var -> per-code bias Bc ----------------
__global__ void k2_finalize() {
    const int b = blockIdx.x, g = blockIdx.y, c = threadIdx.x;
    __shared__ float s_mean, s_sd;
    if (c == 0) {
        float sum = 0.f, ssq = 0.f;
#pragma unroll
        for (int i = 0; i < 32; ++i) { sum += g_part[b][g][i][0]; ssq += g_part[b][g][i][1]; }
        const float invN = 1.f / (float)(VD * L);
        const float mean = sum * invN;
        const float var = ssq * invN - mean * mean;
        s_mean = mean;
        s_sd = sqrtf(var + EPS);
    }
    __syncthreads();
    g_Bc[b][g][c] = s_mean * g_S1[g][c] + (0.5f * g_e2[c] - g_S2[g][c]) * s_sd;
}

// ---------------- K3: dots = X @ M^T, argmax, gather codes -----------------
// 64 tokens x 320 codes / block; As stored DUPLICATED (a,a); Ms via cp.async
// double buffer with precomputed per-thread offsets (no divides in mainloop).
__global__ __launch_bounds__(256, 2) void k3_vq(const float* __restrict__ x,
                                                const float* __restrict__ emb,
                                                float* __restrict__ out) {
    const int b = blockIdx.z, g = blockIdx.y, l0 = blockIdx.x * 64;
    const int tid = threadIdx.x, w = tid >> 5, lane = tid & 31;

    __shared__ __align__(16) float Ms[2][16][NC];    // 2 x 20 KB
    __shared__ __align__(16) float As2[2][16][130];  // duplicated tokens

    const float* xrow = x + ((size_t)(b * L + l0)) * DIM + g * VD;
    const float* Mg = &g_MT[g][0][0];

    const int la = tid >> 2;            // token this thread loads (0..63)
    const int qa = tid & 3;             // k-quad

    // precomputed cp.async offsets for the 5 x 256-thread sweep of 16x320
    unsigned moff[5];
    size_t goff[5];
#pragma unroll
    for (int n = 0; n < 5; ++n) {
        const int idx = tid + n * 256;
        const int r = idx / 80, col = (idx % 80) * 4;
        moff[n] = smem_u32(&Ms[0][r][col]);
        goff[n] = (size_t)r * NC + col;
    }
    const unsigned MsStride = 16 * NC * 4;   // bytes per buffer

    unsigned long long acc[8][5];
#pragma unroll
    for (int i = 0; i < 8; ++i)
#pragma unroll
        for (int j = 0; j < 5; ++j) acc[i][j] = 0ull;

    // prologue: chunk 0
#pragma unroll
    for (int n = 0; n < 5; ++n) cp_async16(moff[n], Mg + goff[n]);
    cp_commit();
    {
        const float4 v = *(const float4*)(xrow + (size_t)la * DIM + qa * 4);
        *(unsigned long long*)&As2[0][qa * 4 + 0][2 * la] = pk2(v.x, v.x);
        *(unsigned long long*)&As2[0][qa * 4 + 1][2 * la] = pk2(v.y, v.y);
        *(unsigned long long*)&As2[0][qa * 4 + 2][2 * la] = pk2(v.z, v.z);
        *(unsigned long long*)&As2[0][qa * 4 + 3][2 * la] = pk2(v.w, v.w);
    }
    cp_wait0();
    __syncthreads();

    int s = 0;
    for (int step = 0; step < 16; ++step) {
        float4 an;
        if (step < 15) {
            const int kb = (step + 1) * 16;
            const float* src = Mg + (size_t)kb * NC;
            const unsigned dbase = (unsigned)((s ^ 1) * MsStride);
#pragma unroll
            for (int n = 0; n < 5; ++n) cp_async16(moff[n] + dbase, src + goff[n]);
            cp_commit();
            an = *(const float4*)(xrow + (size_t)la * DIM + kb + qa * 4);
        }
#pragma unroll
        for (int k = 0; k < 16; ++k) {
            unsigned long long m[5];
#pragma unroll
            for (int j = 0; j < 5; ++j)
                m[j] = *(const unsigned long long*)&Ms[s][k][j * 64 + lane * 2];
#pragma unroll
            for (int i = 0; i < 8; ++i) {
                const unsigned long long ad =
                    *(const unsigned long long*)&As2[s][k][2 * (w * 8 + i)];
#pragma unroll
                for (int j = 0; j < 5; ++j) acc[i][j] = ffma2(ad, m[j], acc[i][j]);
            }
        }
        if (step < 15) {
            const int d = s ^ 1;
            *(unsigned long long*)&As2[d][qa * 4 + 0][2 * la] = pk2(an.x, an.x);
            *(unsigned long long*)&As2[d][qa * 4 + 1][2 * la] = pk2(an.y, an.y);
            *(unsigned long long*)&As2[d][qa * 4 + 2][2 * la] = pk2(an.z, an.z);
            *(unsigned long long*)&As2[d][qa * 4 + 3][2 * la] = pk2(an.w, an.w);
        }
        cp_wait0();
        __syncthreads();
        s ^= 1;
    }

    // bias + argmax (tie-break: lowest code index)
    float2 bc[5];
#pragma unroll
    for (int j = 0; j < 5; ++j)
        bc[j] = *(const float2*)&g_Bc[b][g][j * 64 + lane * 2];

    const unsigned FULL = 0xffffffffu;
    int bestc[8];
#pragma unroll
    for (int i = 0; i < 8; ++i) {
        float bv = -1e30f; int bi = 0x7fffffff;
#pragma unroll
        for (int j = 0; j < 5; ++j) {
            float lo, hi; upk2(acc[i][j], lo, hi);
            const int c0 = j * 64 + lane * 2;
            const float s0 = lo - bc[j].x;
            const float s1 = hi - bc[j].y;
            if (s0 > bv || (s0 == bv && c0 < bi)) { bv = s0; bi = c0; }
            if (s1 > bv || (s1 == bv && (c0 + 1) < bi)) { bv = s1; bi = c0 + 1; }
        }
#pragma unroll
        for (int off = 16; off; off >>= 1) {
            const float ov = __shfl_xor_sync(FULL, bv, off);
            const int oc = __shfl_xor_sync(FULL, bi, off);
            if (ov > bv || (ov == bv && oc < bi)) { bv = ov; bi = oc; }
        }
        bestc[i] = bi;
    }

    // gather: out[b, l, g*VD : (g+1)*VD] = emb[bestc]
    float* orow = out + ((size_t)(b * L + l0 + w * 8)) * DIM + g * VD;
#pragma unroll
    for (int i = 0; i < 8; ++i) {
        const float4* src = (const float4*)(emb + (size_t)bestc[i] * VD);
        float4* dst = (float4*)(orow + (size_t)i * DIM);
        dst[lane] = src[lane];
        dst[lane + 32] = src[lane + 32];
    }
}

// ---------------- launch ---------------------------------------------------
extern "C" void kernel_launch(void* const* d_in, const int* in_sizes, int n_in,
                              void* d_out, int out_size) {
    (void)in_sizes; (void)n_in; (void)out_size;
    const float* x   = (const float*)d_in[0];
    const float* W   = (const float*)d_in[1];
    const float* gw  = (const float*)d_in[2];
    const float* gb  = (const float*)d_in[3];
    const float* emb = (const float*)d_in[4];
    float* out = (float*)d_out;

    k0_prep<<<dim3(NC / 8, G), 256>>>(W, gw, gb, emb);
    k1_stats<<<dim3(2, 16, 32), 256>>>(x, W);
    k2_finalize<<<dim3(BS, G), NC>>>();
    k3_vq<<<dim3(L / 64, G, BS), 256>>>(x, emb, out);
}

// round 9
// speedup vs baseline: 1.3195x; 1.2100x over previous
#include <cuda_runtime.h>
#include <math.h>

namespace {
constexpr int BS = 16, L = 2048, DIM = 512, G = 2, VD = 256, NC = 320;
constexpr float EPS = 1e-5f;
}

// ---------------- scratch (device globals; no allocation allowed) ----------
__device__ float g_MT[G][VD][NC];      // M^T[g][u][c] : dots = x @ MT
__device__ float g_S1[G][NC];
__device__ float g_S2[G][NC];
__device__ float g_e2[NC];
__device__ float g_part[BS][G][32][2]; // per-block partial {sum,sumsq}
__device__ float g_Bc[BS][G][NC];

// ---------------- packed f32x2 helpers (Blackwell FFMA2 pipe) --------------
__device__ __forceinline__ unsigned long long pk2(float lo, float hi) {
    unsigned long long r;
    asm("mov.b64 %0, {%1, %2};" : "=l"(r) : "f"(lo), "f"(hi));
    return r;
}
__device__ __forceinline__ void upk2(unsigned long long v, float &lo, float &hi) {
    asm("mov.b64 {%0, %1}, %2;" : "=f"(lo), "=f"(hi) : "l"(v));
}
__device__ __forceinline__ unsigned long long ffma2(unsigned long long a,
                                                    unsigned long long b,
                                                    unsigned long long c) {
    unsigned long long d;
    asm("fma.rn.f32x2 %0, %1, %2, %3;" : "=l"(d) : "l"(a), "l"(b), "l"(c));
    return d;
}

// ---------------- cp.async helpers -----------------------------------------
__device__ __forceinline__ unsigned smem_u32(const void* p) {
    return (unsigned)__cvta_generic_to_shared(p);
}
__device__ __forceinline__ void cp_async16(unsigned dst, const void* src) {
    asm volatile("cp.async.cg.shared.global [%0], [%1], 16;\n" :: "r"(dst), "l"(src));
}
__device__ __forceinline__ void cp_commit() {
    asm volatile("cp.async.commit_group;\n");
}
__device__ __forceinline__ void cp_wait0() {
    asm volatile("cp.async.wait_group 0;\n" ::: "memory");
}

// ---------------- K0: fold W, gn_weight, emb into M^T; S1/S2/e2 ------------
__global__ void k0_prep(const float* __restrict__ W,
                        const float* __restrict__ gw,
                        const float* __restrict__ gb,
                        const float* __restrict__ emb) {
    const int c0 = blockIdx.x * 8, g = blockIdx.y, tid = threadIdx.x;
    __shared__ float es[8][VD];   // gw-scaled emb rows

    for (int idx = tid; idx < 8 * VD; idx += 256) {
        const int c = idx >> 8, o = idx & 255;
        es[c][o] = emb[(size_t)(c0 + c) * VD + o] * gw[g * VD + o];
    }
    __syncthreads();

    // reductions: warp w owns code c0+w
    const int w = tid >> 5, lane = tid & 31;
    {
        float s1 = 0.f, s2 = 0.f, s3 = 0.f;
        const float* ec = emb + (size_t)(c0 + w) * VD;
        for (int o = lane; o < VD; o += 32) {
            const float e = ec[o];
            s1 = fmaf(e, gw[g * VD + o], s1);
            s2 = fmaf(e, gb[g * VD + o], s2);
            s3 = fmaf(e, e, s3);
        }
        const unsigned FULL = 0xffffffffu;
#pragma unroll
        for (int off = 16; off; off >>= 1) {
            s1 += __shfl_xor_sync(FULL, s1, off);
            s2 += __shfl_xor_sync(FULL, s2, off);
            s3 += __shfl_xor_sync(FULL, s3, off);
        }
        if (lane == 0) {
            g_S1[g][c0 + w] = s1;
            g_S2[g][c0 + w] = s2;
            if (g == 0) g_e2[c0 + w] = s3;
        }
    }

    float acc[8];
#pragma unroll
    for (int c = 0; c < 8; ++c) acc[c] = 0.f;
    const float* Wg = W + (size_t)g * VD * VD + tid;
#pragma unroll 4
    for (int o = 0; o < VD; ++o) {
        const float wv = Wg[(size_t)o * VD];
#pragma unroll
        for (int c = 0; c < 8; ++c) acc[c] = fmaf(wv, es[c][o], acc[c]);
    }
    float4* dst = (float4*)&g_MT[g][tid][c0];
    dst[0] = make_float4(acc[0], acc[1], acc[2], acc[3]);
    dst[1] = make_float4(acc[4], acc[5], acc[6], acc[7]);
}

// ---------------- K1: ze = X_g @ W_g^T, accumulate sum/sumsq ---------------
// 128x128 tile, K-chunks of 16 (halved barrier count vs chunk-8), double
// buffered; R4-proven inner loop (scalar Bs LDS + pk2, LDS.64 token pairs).
__global__ __launch_bounds__(256, 2) void k1_stats(const float* __restrict__ x,
                                                   const float* __restrict__ W) {
    const int b = blockIdx.z >> 1, g = blockIdx.z & 1;
    const int l0 = blockIdx.y * 128, o0 = blockIdx.x * 128;
    const int tid = threadIdx.x;

    __shared__ __align__(16) float As[2][16][128];  // [k][l]
    __shared__ __align__(16) float Bs[2][16][128];  // [k][o]

    const float* Ag = x + ((size_t)(b * L + l0)) * DIM + g * VD;
    const float* Bg = W + (size_t)g * VD * VD + (size_t)o0 * VD;

    const int arow = tid >> 1;          // token row (and o row) this thread loads
    const int acol = (tid & 1) * 8;     // k offset (two float4 per chunk)
    const int tl = (tid >> 4) * 8;      // 8 tokens owned (pairs)
    const int om = tid & 15;            // o = om + 16*j (interleaved)

    unsigned long long acc[4][8];
#pragma unroll
    for (int i = 0; i < 4; ++i)
#pragma unroll
        for (int j = 0; j < 8; ++j) acc[i][j] = 0ull;

    // prologue: chunk 0
    {
        const float4 a0 = *(const float4*)(Ag + (size_t)arow * DIM + acol);
        const float4 a1 = *(const float4*)(Ag + (size_t)arow * DIM + acol + 4);
        const float4 b0 = *(const float4*)(Bg + (size_t)arow * VD + acol);
        const float4 b1 = *(const float4*)(Bg + (size_t)arow * VD + acol + 4);
        As[0][acol + 0][arow] = a0.x; As[0][acol + 1][arow] = a0.y;
        As[0][acol + 2][arow] = a0.z; As[0][acol + 3][arow] = a0.w;
        As[0][acol + 4][arow] = a1.x; As[0][acol + 5][arow] = a1.y;
        As[0][acol + 6][arow] = a1.z; As[0][acol + 7][arow] = a1.w;
        Bs[0][acol + 0][arow] = b0.x; Bs[0][acol + 1][arow] = b0.y;
        Bs[0][acol + 2][arow] = b0.z; Bs[0][acol + 3][arow] = b0.w;
        Bs[0][acol + 4][arow] = b1.x; Bs[0][acol + 5][arow] = b1.y;
        Bs[0][acol + 6][arow] = b1.z; Bs[0][acol + 7][arow] = b1.w;
    }
    __syncthreads();

    int s = 0;
    for (int kc = 0; kc < 16; ++kc) {
        float4 a0, a1, b0, b1;
        if (kc < 15) {
            const int kb = (kc + 1) * 16;
            a0 = *(const float4*)(Ag + (size_t)arow * DIM + kb + acol);
            a1 = *(const float4*)(Ag + (size_t)arow * DIM + kb + acol + 4);
            b0 = *(const float4*)(Bg + (size_t)arow * VD + kb + acol);
            b1 = *(const float4*)(Bg + (size_t)arow * VD + kb + acol + 4);
        }
#pragma unroll
        for (int k = 0; k < 16; ++k) {
            unsigned long long ap[4];
#pragma unroll
            for (int i = 0; i < 4; ++i)
                ap[i] = *(const unsigned long long*)&As[s][k][tl + 2 * i];
#pragma unroll
            for (int j = 0; j < 8; ++j) {
                const float bvv = Bs[s][k][om + 16 * j];
                const unsigned long long bd = pk2(bvv, bvv);
#pragma unroll
                for (int i = 0; i < 4; ++i) acc[i][j] = ffma2(ap[i], bd, acc[i][j]);
            }
        }
        if (kc < 15) {
            const int d = s ^ 1;
            As[d][acol + 0][arow] = a0.x; As[d][acol + 1][arow] = a0.y;
            As[d][acol + 2][arow] = a0.z; As[d][acol + 3][arow] = a0.w;
            As[d][acol + 4][arow] = a1.x; As[d][acol + 5][arow] = a1.y;
            As[d][acol + 6][arow] = a1.z; As[d][acol + 7][arow] = a1.w;
            Bs[d][acol + 0][arow] = b0.x; Bs[d][acol + 1][arow] = b0.y;
            Bs[d][acol + 2][arow] = b0.z; Bs[d][acol + 3][arow] = b0.w;
            Bs[d][acol + 4][arow] = b1.x; Bs[d][acol + 5][arow] = b1.y;
            Bs[d][acol + 6][arow] = b1.z; Bs[d][acol + 7][arow] = b1.w;
        }
        __syncthreads();
        s ^= 1;
    }

    // local sum / sumsq over this thread's 64 outputs
    float ts = 0.f, tss = 0.f;
#pragma unroll
    for (int i = 0; i < 4; ++i)
#pragma unroll
        for (int j = 0; j < 8; ++j) {
            float lo, hi; upk2(acc[i][j], lo, hi);
            ts += lo + hi;
            tss = fmaf(lo, lo, tss); tss = fmaf(hi, hi, tss);
        }
    const unsigned FULL = 0xffffffffu;
#pragma unroll
    for (int off = 16; off; off >>= 1) {
        ts  += __shfl_xor_sync(FULL, ts, off);
        tss += __shfl_xor_sync(FULL, tss, off);
    }
    __shared__ float sred[2][8];
    const int w = tid >> 5, lane = tid & 31;
    if (lane == 0) { sred[0][w] = ts; sred[1][w] = tss; }
    __syncthreads();
    if (tid == 0) {
        float su = 0.f, ss = 0.f;
#pragma unroll
        for (int i = 0; i < 8; ++i) { su += sred[0][i]; ss += sred[1][i]; }
        const int slot = blockIdx.y * 2 + blockIdx.x;
        g_part[b][g][slot][0] = su;
        g_part[b][g][slot][1] = ss;
    }
}

// ---------------- K2: finalize mean/var -> per-code bias Bc ----------------
__global__ void k2_finalize() {
    const int b = blockIdx.x, g = blockIdx.y, c = threadIdx.x;
    __shared__ float s_mean, s_sd;
    if (c == 0) {
        float sum = 0.f, ssq = 0.f;
#pragma unroll
        for (int i = 0; i < 32; ++i) { sum += g_part[b][g][i][0]; ssq += g_part[b][g][i][1]; }
        const float invN = 1.f / (float)(VD * L);
        const float mean = sum * invN;
        const float var = ssq * invN - mean * mean;
        s_mean = mean;
        s_sd = sqrtf(var + EPS);
    }
    __syncthreads();
    g_Bc[b][g][c] = s_mean * g_S1[g][c] + (0.5f * g_e2[c] - g_S2[g][c]) * s_sd;
}

// ---------------- K3: dots = X @ M^T, argmax, gather codes -----------------
// EXACT R4 version (204us, fma 69.5%): 64 tokens x 320 codes / block,
// K chunks of 16, cp.async double-buffered Ms, scalar As broadcast + pk2.
__global__ __launch_bounds__(256, 2) void k3_vq(const float* __restrict__ x,
                                                const float* __restrict__ emb,
                                                float* __restrict__ out) {
    const int b = blockIdx.z, g = blockIdx.y, l0 = blockIdx.x * 64;
    const int tid = threadIdx.x, w = tid >> 5, lane = tid & 31;

    __shared__ __align__(16) float Ms[2][16][NC];   // 2 x 20 KB
    __shared__ float As[2][16][66];                 // row 66: conflict-free STS

    const float* xrow = x + ((size_t)(b * L + l0)) * DIM + g * VD;
    const float* Mg = &g_MT[g][0][0];

    const int la = tid >> 2;            // token this thread loads (0..63)
    const int qa = tid & 3;             // k-quad

    unsigned long long acc[8][5];
#pragma unroll
    for (int i = 0; i < 8; ++i)
#pragma unroll
        for (int j = 0; j < 5; ++j) acc[i][j] = 0ull;

    // prologue: chunk 0
#pragma unroll
    for (int n = 0; n < 5; ++n) {
        const int idx = tid + n * 256;
        const int r = idx / 80, col = (idx % 80) * 4;
        cp_async16(smem_u32(&Ms[0][r][col]), Mg + (size_t)r * NC + col);
    }
    cp_commit();
    {
        const float4 v = *(const float4*)(xrow + (size_t)la * DIM + qa * 4);
        As[0][qa * 4 + 0][la] = v.x; As[0][qa * 4 + 1][la] = v.y;
        As[0][qa * 4 + 2][la] = v.z; As[0][qa * 4 + 3][la] = v.w;
    }
    cp_wait0();
    __syncthreads();

    int s = 0;
    for (int step = 0; step < 16; ++step) {
        float4 an;
        if (step < 15) {
            const int kb = (step + 1) * 16;
#pragma unroll
            for (int n = 0; n < 5; ++n) {
                const int idx = tid + n * 256;
                const int r = idx / 80, col = (idx % 80) * 4;
                cp_async16(smem_u32(&Ms[s ^ 1][r][col]),
                           Mg + (size_t)(kb + r) * NC + col);
            }
            cp_commit();
            an = *(const float4*)(xrow + (size_t)la * DIM + kb + qa * 4);
        }
#pragma unroll
        for (int k = 0; k < 16; ++k) {
            unsigned long long m[5];
#pragma unroll
            for (int j = 0; j < 5; ++j)
                m[j] = *(const unsigned long long*)&Ms[s][k][j * 64 + lane * 2];
#pragma unroll
            for (int i = 0; i < 8; ++i) {
                const float av = As[s][k][w * 8 + i];
                const unsigned long long ad = pk2(av, av);
#pragma unroll
                for (int j = 0; j < 5; ++j) acc[i][j] = ffma2(ad, m[j], acc[i][j]);
            }
        }
        if (step < 15) {
            const int d = s ^ 1;
            As[d][qa * 4 + 0][la] = an.x; As[d][qa * 4 + 1][la] = an.y;
            As[d][qa * 4 + 2][la] = an.z; As[d][qa * 4 + 3][la] = an.w;
        }
        cp_wait0();
        __syncthreads();
        s ^= 1;
    }

    // bias + argmax (tie-break: lowest code index)
    float2 bc[5];
#pragma unroll
    for (int j = 0; j < 5; ++j)
        bc[j] = *(const float2*)&g_Bc[b][g][j * 64 + lane * 2];

    const unsigned FULL = 0xffffffffu;
    int bestc[8];
#pragma unroll
    for (int i = 0; i < 8; ++i) {
        float bv = -1e30f; int bi = 0x7fffffff;
#pragma unroll
        for (int j = 0; j < 5; ++j) {
            float lo, hi; upk2(acc[i][j], lo, hi);
            const int c0 = j * 64 + lane * 2;
            const float s0 = lo - bc[j].x;
            const float s1 = hi - bc[j].y;
            if (s0 > bv || (s0 == bv && c0 < bi)) { bv = s0; bi = c0; }
            if (s1 > bv || (s1 == bv && (c0 + 1) < bi)) { bv = s1; bi = c0 + 1; }
        }
#pragma unroll
        for (int off = 16; off; off >>= 1) {
            const float ov = __shfl_xor_sync(FULL, bv, off);
            const int oc = __shfl_xor_sync(FULL, bi, off);
            if (ov > bv || (ov == bv && oc < bi)) { bv = ov; bi = oc; }
        }
        bestc[i] = bi;
    }

    // gather: out[b, l, g*VD : (g+1)*VD] = emb[bestc]
    float* orow = out + ((size_t)(b * L + l0 + w * 8)) * DIM + g * VD;
#pragma unroll
    for (int i = 0; i < 8; ++i) {
        const float4* src = (const float4*)(emb + (size_t)bestc[i] * VD);
        float4* dst = (float4*)(orow + (size_t)i * DIM);
        dst[lane] = src[lane];
        dst[lane + 32] = src[lane + 32];
    }
}

// ---------------- launch ---------------------------------------------------
extern "C" void kernel_launch(void* const* d_in, const int* in_sizes, int n_in,
                              void* d_out, int out_size) {
    (void)in_sizes; (void)n_in; (void)out_size;
    const float* x   = (const float*)d_in[0];
    const float* W   = (const float*)d_in[1];
    const float* gw  = (const float*)d_in[2];
    const float* gb  = (const float*)d_in[3];
    const float* emb = (const float*)d_in[4];
    float* out = (float*)d_out;

    k0_prep<<<dim3(NC / 8, G), 256>>>(W, gw, gb, emb);
    k1_stats<<<dim3(2, 16, 32), 256>>>(x, W);
    k2_finalize<<<dim3(BS, G), NC>>>();
    k3_vq<<<dim3(L / 64, G, BS), 256>>>(x, emb, out);
}

// round 11
// speedup vs baseline: 1.6830x; 1.2755x over previous
#include <cuda_runtime.h>
#include <math.h>

namespace {
constexpr int BS = 16, L = 2048, DIM = 512, G = 2, VD = 256, NC = 320;
constexpr float EPS = 1e-5f;
}

// ---------------- scratch (device globals; no allocation allowed) ----------
__device__ float g_MT[G][VD][NC];      // M^T[g][u][c] : dots = x @ MT
__device__ float g_S1[G][NC];
__device__ float g_S2[G][NC];
__device__ float g_e2[NC];
__device__ float g_part[BS][G][32][2]; // per-block partial {sum,sumsq}
__device__ float g_Bc[BS][G][NC];

// ---------------- packed f32x2 helpers (Blackwell FFMA2 pipe) --------------
__device__ __forceinline__ unsigned long long pk2(float lo, float hi) {
    unsigned long long r;
    asm("mov.b64 %0, {%1, %2};" : "=l"(r) : "f"(lo), "f"(hi));
    return r;
}
__device__ __forceinline__ void upk2(unsigned long long v, float &lo, float &hi) {
    asm("mov.b64 {%0, %1}, %2;" : "=f"(lo), "=f"(hi) : "l"(v));
}
__device__ __forceinline__ unsigned long long ffma2(unsigned long long a,
                                                    unsigned long long b,
                                                    unsigned long long c) {
    unsigned long long d;
    asm("fma.rn.f32x2 %0, %1, %2, %3;" : "=l"(d) : "l"(a), "l"(b), "l"(c));
    return d;
}

// ---------------- tf32 helpers ----------------------------------------------
__device__ __forceinline__ unsigned f2tf32(float f) {
    unsigned u;
    asm("cvt.rna.tf32.f32 %0, %1;" : "=r"(u) : "f"(f));
    return u;
}
__device__ __forceinline__ void mma_tf32(float c[4],
                                         unsigned a0, unsigned a1, unsigned a2, unsigned a3,
                                         unsigned b0, unsigned b1) {
    asm volatile(
        "mma.sync.aligned.m16n8k8.row.col.f32.tf32.tf32.f32 "
        "{%0,%1,%2,%3}, {%4,%5,%6,%7}, {%8,%9}, {%0,%1,%2,%3};"
        : "+f"(c[0]), "+f"(c[1]), "+f"(c[2]), "+f"(c[3])
        : "r"(a0), "r"(a1), "r"(a2), "r"(a3), "r"(b0), "r"(b1));
}

// ---------------- cp.async helpers -----------------------------------------
__device__ __forceinline__ unsigned smem_u32(const void* p) {
    return (unsigned)__cvta_generic_to_shared(p);
}
__device__ __forceinline__ void cp_async16(unsigned dst, const void* src) {
    asm volatile("cp.async.cg.shared.global [%0], [%1], 16;\n" :: "r"(dst), "l"(src));
}
__device__ __forceinline__ void cp_commit() {
    asm volatile("cp.async.commit_group;\n");
}
__device__ __forceinline__ void cp_wait0() {
    asm volatile("cp.async.wait_group 0;\n" ::: "memory");
}

// ---------------- K0: fold W, gn_weight, emb into M^T; S1/S2/e2 ------------
__global__ void k0_prep(const float* __restrict__ W,
                        const float* __restrict__ gw,
                        const float* __restrict__ gb,
                        const float* __restrict__ emb) {
    const int c0 = blockIdx.x * 8, g = blockIdx.y, tid = threadIdx.x;
    __shared__ float es[8][VD];   // gw-scaled emb rows

    for (int idx = tid; idx < 8 * VD; idx += 256) {
        const int c = idx >> 8, o = idx & 255;
        es[c][o] = emb[(size_t)(c0 + c) * VD + o] * gw[g * VD + o];
    }
    __syncthreads();

    // reductions: warp w owns code c0+w
    const int w = tid >> 5, lane = tid & 31;
    {
        float s1 = 0.f, s2 = 0.f, s3 = 0.f;
        const float* ec = emb + (size_t)(c0 + w) * VD;
        for (int o = lane; o < VD; o += 32) {
            const float e = ec[o];
            s1 = fmaf(e, gw[g * VD + o], s1);
            s2 = fmaf(e, gb[g * VD + o], s2);
            s3 = fmaf(e, e, s3);
        }
        const unsigned FULL = 0xffffffffu;
#pragma unroll
        for (int off = 16; off; off >>= 1) {
            s1 += __shfl_xor_sync(FULL, s1, off);
            s2 += __shfl_xor_sync(FULL, s2, off);
            s3 += __shfl_xor_sync(FULL, s3, off);
        }
        if (lane == 0) {
            g_S1[g][c0 + w] = s1;
            g_S2[g][c0 + w] = s2;
            if (g == 0) g_e2[c0 + w] = s3;
        }
    }

    float acc[8];
#pragma unroll
    for (int c = 0; c < 8; ++c) acc[c] = 0.f;
    const float* Wg = W + (size_t)g * VD * VD + tid;
#pragma unroll 4
    for (int o = 0; o < VD; ++o) {
        const float wv = Wg[(size_t)o * VD];
#pragma unroll
        for (int c = 0; c < 8; ++c) acc[c] = fmaf(wv, es[c][o], acc[c]);
    }
    float4* dst = (float4*)&g_MT[g][tid][c0];
    dst[0] = make_float4(acc[0], acc[1], acc[2], acc[3]);
    dst[1] = make_float4(acc[4], acc[5], acc[6], acc[7]);
}

// ---------------- K1: ze = X_g @ W_g^T via tf32 mma.sync; sum/sumsq --------
// 128(l) x 128(o) tile per CTA (256 thr, 8 warps), K chunks of 16, double
// buffered smem (tf32-converted, [row][k] pad-4). Warp tile 32x64.
// Stats only -> any fragment->element mapping is fine (order-agnostic sum).
__global__ __launch_bounds__(256, 2) void k1_stats(const float* __restrict__ x,
                                                   const float* __restrict__ W) {
    const int b = blockIdx.z >> 1, g = blockIdx.z & 1;
    const int l0 = blockIdx.y * 128, o0 = blockIdx.x * 128;
    const int tid = threadIdx.x, w = tid >> 5, lane = tid & 31;

    __shared__ unsigned As[2][128][20];   // [l][k] pad 4 (stride 20: frag-conflict-free)
    __shared__ unsigned Bs[2][128][20];   // [o][k]

    const float* Ag = x + ((size_t)(b * L + l0)) * DIM + g * VD;
    const float* Bg = W + (size_t)g * VD * VD + (size_t)o0 * VD;

    const int lrow = tid >> 1;            // row this thread stages (both arrays)
    const int lcol = (tid & 1) * 8;       // k offset (two float4)

    const int mb = (w >> 1) * 32;         // warp rows: 32
    const int nb = (w & 1) * 64;          // warp cols: 64
    const int fr = lane >> 2, fc = lane & 3;

    float c[2][8][4];
#pragma unroll
    for (int mt = 0; mt < 2; ++mt)
#pragma unroll
        for (int nt = 0; nt < 8; ++nt)
#pragma unroll
            for (int q = 0; q < 4; ++q) c[mt][nt][q] = 0.f;

    // stage chunk 0
    {
        const float4 a0 = *(const float4*)(Ag + (size_t)lrow * DIM + lcol);
        const float4 a1 = *(const float4*)(Ag + (size_t)lrow * DIM + lcol + 4);
        const float4 b0 = *(const float4*)(Bg + (size_t)lrow * VD + lcol);
        const float4 b1 = *(const float4*)(Bg + (size_t)lrow * VD + lcol + 4);
        As[0][lrow][lcol + 0] = f2tf32(a0.x); As[0][lrow][lcol + 1] = f2tf32(a0.y);
        As[0][lrow][lcol + 2] = f2tf32(a0.z); As[0][lrow][lcol + 3] = f2tf32(a0.w);
        As[0][lrow][lcol + 4] = f2tf32(a1.x); As[0][lrow][lcol + 5] = f2tf32(a1.y);
        As[0][lrow][lcol + 6] = f2tf32(a1.z); As[0][lrow][lcol + 7] = f2tf32(a1.w);
        Bs[0][lrow][lcol + 0] = f2tf32(b0.x); Bs[0][lrow][lcol + 1] = f2tf32(b0.y);
        Bs[0][lrow][lcol + 2] = f2tf32(b0.z); Bs[0][lrow][lcol + 3] = f2tf32(b0.w);
        Bs[0][lrow][lcol + 4] = f2tf32(b1.x); Bs[0][lrow][lcol + 5] = f2tf32(b1.y);
        Bs[0][lrow][lcol + 6] = f2tf32(b1.z); Bs[0][lrow][lcol + 7] = f2tf32(b1.w);
    }
    __syncthreads();

    int s = 0;
    for (int kc = 0; kc < 16; ++kc) {
        float4 pa0, pa1, pb0, pb1;
        if (kc < 15) {
            const int kb = (kc + 1) * 16;
            pa0 = *(const float4*)(Ag + (size_t)lrow * DIM + kb + lcol);
            pa1 = *(const float4*)(Ag + (size_t)lrow * DIM + kb + lcol + 4);
            pb0 = *(const float4*)(Bg + (size_t)lrow * VD + kb + lcol);
            pb1 = *(const float4*)(Bg + (size_t)lrow * VD + kb + lcol + 4);
        }
#pragma unroll
        for (int k8 = 0; k8 < 2; ++k8) {
            const int kk = k8 * 8;
            unsigned af[2][4];
#pragma unroll
            for (int mt = 0; mt < 2; ++mt) {
                const int rb = mb + mt * 16;
                af[mt][0] = As[s][rb + fr][kk + fc];
                af[mt][1] = As[s][rb + fr + 8][kk + fc];
                af[mt][2] = As[s][rb + fr][kk + fc + 4];
                af[mt][3] = As[s][rb + fr + 8][kk + fc + 4];
            }
#pragma unroll
            for (int nt = 0; nt < 8; ++nt) {
                const int cb = nb + nt * 8;
                const unsigned b0 = Bs[s][cb + fr][kk + fc];
                const unsigned b1 = Bs[s][cb + fr][kk + fc + 4];
#pragma unroll
                for (int mt = 0; mt < 2; ++mt)
                    mma_tf32(c[mt][nt], af[mt][0], af[mt][1], af[mt][2], af[mt][3], b0, b1);
            }
        }
        if (kc < 15) {
            const int d = s ^ 1;
            As[d][lrow][lcol + 0] = f2tf32(pa0.x); As[d][lrow][lcol + 1] = f2tf32(pa0.y);
            As[d][lrow][lcol + 2] = f2tf32(pa0.z); As[d][lrow][lcol + 3] = f2tf32(pa0.w);
            As[d][lrow][lcol + 4] = f2tf32(pa1.x); As[d][lrow][lcol + 5] = f2tf32(pa1.y);
            As[d][lrow][lcol + 6] = f2tf32(pa1.z); As[d][lrow][lcol + 7] = f2tf32(pa1.w);
            Bs[d][lrow][lcol + 0] = f2tf32(pb0.x); Bs[d][lrow][lcol + 1] = f2tf32(pb0.y);
            Bs[d][lrow][lcol + 2] = f2tf32(pb0.z); Bs[d][lrow][lcol + 3] = f2tf32(pb0.w);
            Bs[d][lrow][lcol + 4] = f2tf32(pb1.x); Bs[d][lrow][lcol + 5] = f2tf32(pb1.y);
            Bs[d][lrow][lcol + 6] = f2tf32(pb1.z); Bs[d][lrow][lcol + 7] = f2tf32(pb1.w);
        }
        __syncthreads();
        s ^= 1;
    }

    // sum / sumsq over this thread's 64 ze values
    float ts = 0.f, tss = 0.f;
#pragma unroll
    for (int mt = 0; mt < 2; ++mt)
#pragma unroll
        for (int nt = 0; nt < 8; ++nt)
#pragma unroll
            for (int q = 0; q < 4; ++q) {
                const float v = c[mt][nt][q];
                ts += v;
                tss = fmaf(v, v, tss);
            }
    const unsigned FULL = 0xffffffffu;
#pragma unroll
    for (int off = 16; off; off >>= 1) {
        ts  += __shfl_xor_sync(FULL, ts, off);
        tss += __shfl_xor_sync(FULL, tss, off);
    }
    __shared__ float sred[2][8];
    if (lane == 0) { sred[0][w] = ts; sred[1][w] = tss; }
    __syncthreads();
    if (tid == 0) {
        float su = 0.f, ss = 0.f;
#pragma unroll
        for (int i = 0; i < 8; ++i) { su += sred[0][i]; ss += sred[1][i]; }
        const int slot = blockIdx.y * 2 + blockIdx.x;
        g_part[b][g][slot][0] = su;
        g_part[b][g][slot][1] = ss;
    }
}

// ---------------- K2: finalize mean/var -> per-code bias Bc ----------------
__global__ void k2_finalize() {
    const int b = blockIdx.x, g = blockIdx.y, c = threadIdx.x;
    __shared__ float s_mean, s_sd;
    if (c == 0) {
        float sum = 0.f, ssq = 0.f;
#pragma unroll
        for (int i = 0; i < 32; ++i) { sum += g_part[b][g][i][0]; ssq += g_part[b][g][i][1]; }
        const float invN = 1.f / (float)(VD * L);
        const float mean = sum * invN;
        const float var = ssq * invN - mean * mean;
        s_mean = mean;
        s_sd = sqrtf(var + EPS);
    }
    __syncthreads();
    g_Bc[b][g][c] = s_mean * g_S1[g][c] + (0.5f * g_e2[c] - g_S2[g][c]) * s_sd;
}

// ---------------- K3: dots = X @ M^T, argmax, gather codes -----------------
// Proven R4/R9 version (204us): 64 tokens x 320 codes / block, K chunks of
// 16, cp.async double-buffered Ms, scalar As broadcast + pk2. DO NOT TOUCH.
__global__ __launch_bounds__(256, 2) void k3_vq(const float* __restrict__ x,
                                                const float* __restrict__ emb,
                                                float* __restrict__ out) {
    const int b = blockIdx.z, g = blockIdx.y, l0 = blockIdx.x * 64;
    const int tid = threadIdx.x, w = tid >> 5, lane = tid & 31;

    __shared__ __align__(16) float Ms[2][16][NC];   // 2 x 20 KB
    __shared__ float As[2][16][66];                 // row 66: conflict-free STS

    const float* xrow = x + ((size_t)(b * L + l0)) * DIM + g * VD;
    const float* Mg = &g_MT[g][0][0];

    const int la = tid >> 2;            // token this thread loads (0..63)
    const int qa = tid & 3;             // k-quad

    unsigned long long acc[8][5];
#pragma unroll
    for (int i = 0; i < 8; ++i)
#pragma unroll
        for (int j = 0; j < 5; ++j) acc[i][j] = 0ull;

    // prologue: chunk 0
#pragma unroll
    for (int n = 0; n < 5; ++n) {
        const int idx = tid + n * 256;
        const int r = idx / 80, col = (idx % 80) * 4;
        cp_async16(smem_u32(&Ms[0][r][col]), Mg + (size_t)r * NC + col);
    }
    cp_commit();
    {
        const float4 v = *(const float4*)(xrow + (size_t)la * DIM + qa * 4);
        As[0][qa * 4 + 0][la] = v.x; As[0][qa * 4 + 1][la] = v.y;
        As[0][qa * 4 + 2][la] = v.z; As[0][qa * 4 + 3][la] = v.w;
    }
    cp_wait0();
    __syncthreads();

    int s = 0;
    for (int step = 0; step < 16; ++step) {
        float4 an;
        if (step < 15) {
            const int kb = (step + 1) * 16;
#pragma unroll
            for (int n = 0; n < 5; ++n) {
                const int idx = tid + n * 256;
                const int r = idx / 80, col = (idx % 80) * 4;
                cp_async16(smem_u32(&Ms[s ^ 1][r][col]),
                           Mg + (size_t)(kb + r) * NC + col);
            }
            cp_commit();
            an = *(const float4*)(xrow + (size_t)la * DIM + kb + qa * 4);
        }
#pragma unroll
        for (int k = 0; k < 16; ++k) {
            unsigned long long m[5];
#pragma unroll
            for (int j = 0; j < 5; ++j)
                m[j] = *(const unsigned long long*)&Ms[s][k][j * 64 + lane * 2];
#pragma unroll
            for (int i = 0; i < 8; ++i) {
                const float av = As[s][k][w * 8 + i];
                const unsigned long long ad = pk2(av, av);
#pragma unroll
                for (int j = 0; j < 5; ++j) acc[i][j] = ffma2(ad, m[j], acc[i][j]);
            }
        }
        if (step < 15) {
            const int d = s ^ 1;
            As[d][qa * 4 + 0][la] = an.x; As[d][qa * 4 + 1][la] = an.y;
            As[d][qa * 4 + 2][la] = an.z; As[d][qa * 4 + 3][la] = an.w;
        }
        cp_wait0();
        __syncthreads();
        s ^= 1;
    }

    // bias + argmax (tie-break: lowest code index)
    float2 bc[5];
#pragma unroll
    for (int j = 0; j < 5; ++j)
        bc[j] = *(const float2*)&g_Bc[b][g][j * 64 + lane * 2];

    const unsigned FULL = 0xffffffffu;
    int bestc[8];
#pragma unroll
    for (int i = 0; i < 8; ++i) {
        float bv = -1e30f; int bi = 0x7fffffff;
#pragma unroll
        for (int j = 0; j < 5; ++j) {
            float lo, hi; upk2(acc[i][j], lo, hi);
            const int c0 = j * 64 + lane * 2;
            const float s0 = lo - bc[j].x;
            const float s1 = hi - bc[j].y;
            if (s0 > bv || (s0 == bv && c0 < bi)) { bv = s0; bi = c0; }
            if (s1 > bv || (s1 == bv && (c0 + 1) < bi)) { bv = s1; bi = c0 + 1; }
        }
#pragma unroll
        for (int off = 16; off; off >>= 1) {
            const float ov = __shfl_xor_sync(FULL, bv, off);
            const int oc = __shfl_xor_sync(FULL, bi, off);
            if (ov > bv || (ov == bv && oc < bi)) { bv = ov; bi = oc; }
        }
        bestc[i] = bi;
    }

    // gather: out[b, l, g*VD : (g+1)*VD] = emb[bestc]
    float* orow = out + ((size_t)(b * L + l0 + w * 8)) * DIM + g * VD;
#pragma unroll
    for (int i = 0; i < 8; ++i) {
        const float4* src = (const float4*)(emb + (size_t)bestc[i] * VD);
        float4* dst = (float4*)(orow + (size_t)i * DIM);
        dst[lane] = src[lane];
        dst[lane + 32] = src[lane + 32];
    }
}

// ---------------- launch ---------------------------------------------------
extern "C" void kernel_launch(void* const* d_in, const int* in_sizes, int n_in,
                              void* d_out, int out_size) {
    (void)in_sizes; (void)n_in; (void)out_size;
    const float* x   = (const float*)d_in[0];
    const float* W   = (const float*)d_in[1];
    const float* gw  = (const float*)d_in[2];
    const float* gb  = (const float*)d_in[3];
    const float* emb = (const float*)d_in[4];
    float* out = (float*)d_out;

    k0_prep<<<dim3(NC / 8, G), 256>>>(W, gw, gb, emb);
    k1_stats<<<dim3(2, 16, 32), 256>>>(x, W);
    k2_finalize<<<dim3(BS, G), NC>>>();
    k3_vq<<<dim3(L / 64, G, BS), 256>>>(x, emb, out);
}

// round 12
// speedup vs baseline: 1.7503x; 1.0400x over previous
#include <cuda_runtime.h>
#include <math.h>

namespace {
constexpr int BS = 16, L = 2048, DIM = 512, G = 2, VD = 256, NC = 320;
constexpr float EPS = 1e-5f;
}

// ---------------- scratch (device globals; no allocation allowed) ----------
__device__ float g_MT[G][VD][NC];      // M^T[g][u][c] : dots = x @ MT
__device__ float g_S1[G][NC];
__device__ float g_S2[G][NC];
__device__ float g_e2[NC];
__device__ float g_part[BS][G][32][2]; // per-block partial {sum,sumsq}
__device__ float g_Bc[BS][G][NC];

// ---------------- packed f32x2 helpers (Blackwell FFMA2 pipe) --------------
__device__ __forceinline__ unsigned long long pk2(float lo, float hi) {
    unsigned long long r;
    asm("mov.b64 %0, {%1, %2};" : "=l"(r) : "f"(lo), "f"(hi));
    return r;
}
__device__ __forceinline__ void upk2(unsigned long long v, float &lo, float &hi) {
    asm("mov.b64 {%0, %1}, %2;" : "=f"(lo), "=f"(hi) : "l"(v));
}
__device__ __forceinline__ unsigned long long ffma2(unsigned long long a,
                                                    unsigned long long b,
                                                    unsigned long long c) {
    unsigned long long d;
    asm("fma.rn.f32x2 %0, %1, %2, %3;" : "=l"(d) : "l"(a), "l"(b), "l"(c));
    return d;
}

// ---------------- tf32 mma (raw fp32 bits = round-toward-zero tf32) --------
__device__ __forceinline__ void mma_tf32(float c[4],
                                         unsigned a0, unsigned a1, unsigned a2, unsigned a3,
                                         unsigned b0, unsigned b1) {
    asm volatile(
        "mma.sync.aligned.m16n8k8.row.col.f32.tf32.tf32.f32 "
        "{%0,%1,%2,%3}, {%4,%5,%6,%7}, {%8,%9}, {%0,%1,%2,%3};"
        : "+f"(c[0]), "+f"(c[1]), "+f"(c[2]), "+f"(c[3])
        : "r"(a0), "r"(a1), "r"(a2), "r"(a3), "r"(b0), "r"(b1));
}

// ---------------- cp.async helpers -----------------------------------------
__device__ __forceinline__ unsigned smem_u32(const void* p) {
    return (unsigned)__cvta_generic_to_shared(p);
}
__device__ __forceinline__ void cp_async16(unsigned dst, const void* src) {
    asm volatile("cp.async.cg.shared.global [%0], [%1], 16;\n" :: "r"(dst), "l"(src));
}
__device__ __forceinline__ void cp_commit() {
    asm volatile("cp.async.commit_group;\n");
}
__device__ __forceinline__ void cp_wait0() {
    asm volatile("cp.async.wait_group 0;\n" ::: "memory");
}

// ---------------- K0: fold W, gn_weight, emb into M^T; S1/S2/e2 ------------
__global__ void k0_prep(const float* __restrict__ W,
                        const float* __restrict__ gw,
                        const float* __restrict__ gb,
                        const float* __restrict__ emb) {
    const int c0 = blockIdx.x * 8, g = blockIdx.y, tid = threadIdx.x;
    __shared__ float es[8][VD];   // gw-scaled emb rows

    for (int idx = tid; idx < 8 * VD; idx += 256) {
        const int c = idx >> 8, o = idx & 255;
        es[c][o] = emb[(size_t)(c0 + c) * VD + o] * gw[g * VD + o];
    }
    __syncthreads();

    // reductions: warp w owns code c0+w
    const int w = tid >> 5, lane = tid & 31;
    {
        float s1 = 0.f, s2 = 0.f, s3 = 0.f;
        const float* ec = emb + (size_t)(c0 + w) * VD;
        for (int o = lane; o < VD; o += 32) {
            const float e = ec[o];
            s1 = fmaf(e, gw[g * VD + o], s1);
            s2 = fmaf(e, gb[g * VD + o], s2);
            s3 = fmaf(e, e, s3);
        }
        const unsigned FULL = 0xffffffffu;
#pragma unroll
        for (int off = 16; off; off >>= 1) {
            s1 += __shfl_xor_sync(FULL, s1, off);
            s2 += __shfl_xor_sync(FULL, s2, off);
            s3 += __shfl_xor_sync(FULL, s3, off);
        }
        if (lane == 0) {
            g_S1[g][c0 + w] = s1;
            g_S2[g][c0 + w] = s2;
            if (g == 0) g_e2[c0 + w] = s3;
        }
    }

    float acc[8];
#pragma unroll
    for (int c = 0; c < 8; ++c) acc[c] = 0.f;
    const float* Wg = W + (size_t)g * VD * VD + tid;
#pragma unroll 4
    for (int o = 0; o < VD; ++o) {
        const float wv = Wg[(size_t)o * VD];
#pragma unroll
        for (int c = 0; c < 8; ++c) acc[c] = fmaf(wv, es[c][o], acc[c]);
    }
    float4* dst = (float4*)&g_MT[g][tid][c0];
    dst[0] = make_float4(acc[0], acc[1], acc[2], acc[3]);
    dst[1] = make_float4(acc[4], acc[5], acc[6], acc[7]);
}

// ---------------- K1: ze = X_g @ W_g^T via tf32 mma; sum/sumsq -------------
// Raw fp32 bits fed to tf32 mma (rz truncation — fine for stats).
// cp.async staging, 128x128 tile, K chunks of 16, double buffered, [row][20].
__global__ __launch_bounds__(256, 2) void k1_stats(const float* __restrict__ x,
                                                   const float* __restrict__ W) {
    const int b = blockIdx.z >> 1, g = blockIdx.z & 1;
    const int l0 = blockIdx.y * 128, o0 = blockIdx.x * 128;
    const int tid = threadIdx.x, w = tid >> 5, lane = tid & 31;

    __shared__ __align__(16) unsigned As[2][128][20];   // [l][k] pad-4 (frag-conflict-free)
    __shared__ __align__(16) unsigned Bs[2][128][20];   // [o][k]

    const float* Ag = x + ((size_t)(b * L + l0)) * DIM + g * VD;
    const float* Bg = W + (size_t)g * VD * VD + (size_t)o0 * VD;

    const int lrow = tid >> 1;            // row this thread stages (both arrays)
    const int lcol = (tid & 1) * 8;       // k offset (two cp16 at +0, +4)

    const int mb = (w >> 1) * 32;         // warp rows: 32
    const int nb = (w & 1) * 64;          // warp cols: 64
    const int fr = lane >> 2, fc = lane & 3;

    float c[2][8][4];
#pragma unroll
    for (int mt = 0; mt < 2; ++mt)
#pragma unroll
        for (int nt = 0; nt < 8; ++nt)
#pragma unroll
            for (int q = 0; q < 4; ++q) c[mt][nt][q] = 0.f;

    const unsigned dA0 = smem_u32(&As[0][lrow][lcol]);
    const unsigned dB0 = smem_u32(&Bs[0][lrow][lcol]);
    const unsigned bufA = (unsigned)(128 * 20 * 4);  // bytes per As buffer
    const float* srcA = Ag + (size_t)lrow * DIM + lcol;
    const float* srcB = Bg + (size_t)lrow * VD + lcol;

    // stage chunk 0
    cp_async16(dA0, srcA);      cp_async16(dA0 + 16, srcA + 4);
    cp_async16(dB0, srcB);      cp_async16(dB0 + 16, srcB + 4);
    cp_commit();
    cp_wait0();
    __syncthreads();

    int s = 0;
    for (int kc = 0; kc < 16; ++kc) {
        if (kc < 15) {
            const int kb = (kc + 1) * 16;
            const unsigned off = (unsigned)((s ^ 1) * bufA);
            cp_async16(dA0 + off, srcA + kb);
            cp_async16(dA0 + off + 16, srcA + kb + 4);
            cp_async16(dB0 + off, srcB + kb);
            cp_async16(dB0 + off + 16, srcB + kb + 4);
            cp_commit();
        }
#pragma unroll
        for (int k8 = 0; k8 < 2; ++k8) {
            const int kk = k8 * 8;
            unsigned af[2][4];
#pragma unroll
            for (int mt = 0; mt < 2; ++mt) {
                const int rb = mb + mt * 16;
                af[mt][0] = As[s][rb + fr][kk + fc];
                af[mt][1] = As[s][rb + fr + 8][kk + fc];
                af[mt][2] = As[s][rb + fr][kk + fc + 4];
                af[mt][3] = As[s][rb + fr + 8][kk + fc + 4];
            }
#pragma unroll
            for (int nt = 0; nt < 8; ++nt) {
                const int cb = nb + nt * 8;
                const unsigned b0 = Bs[s][cb + fr][kk + fc];
                const unsigned b1 = Bs[s][cb + fr][kk + fc + 4];
#pragma unroll
                for (int mt = 0; mt < 2; ++mt)
                    mma_tf32(c[mt][nt], af[mt][0], af[mt][1], af[mt][2], af[mt][3], b0, b1);
            }
        }
        if (kc < 15) cp_wait0();
        __syncthreads();
        s ^= 1;
    }

    // sum / sumsq over this thread's 64 ze values
    float ts = 0.f, tss = 0.f;
#pragma unroll
    for (int mt = 0; mt < 2; ++mt)
#pragma unroll
        for (int nt = 0; nt < 8; ++nt)
#pragma unroll
            for (int q = 0; q < 4; ++q) {
                const float v = c[mt][nt][q];
                ts += v;
                tss = fmaf(v, v, tss);
            }
    const unsigned FULL = 0xffffffffu;
#pragma unroll
    for (int off = 16; off; off >>= 1) {
        ts  += __shfl_xor_sync(FULL, ts, off);
        tss += __shfl_xor_sync(FULL, tss, off);
    }
    __shared__ float sred[2][8];
    if (lane == 0) { sred[0][w] = ts; sred[1][w] = tss; }
    __syncthreads();
    if (tid == 0) {
        float su = 0.f, ss = 0.f;
#pragma unroll
        for (int i = 0; i < 8; ++i) { su += sred[0][i]; ss += sred[1][i]; }
        const int slot = blockIdx.y * 2 + blockIdx.x;
        g_part[b][g][slot][0] = su;
        g_part[b][g][slot][1] = ss;
    }
}

// ---------------- K2: finalize mean/var -> per-code bias Bc ----------------
__global__ void k2_finalize() {
    const int b = blockIdx.x, g = blockIdx.y, c = threadIdx.x;
    __shared__ float s_mean, s_sd;
    if (c == 0) {
        float sum = 0.f, ssq = 0.f;
#pragma unroll
        for (int i = 0; i < 32; ++i) { sum += g_part[b][g][i][0]; ssq += g_part[b][g][i][1]; }
        const float invN = 1.f / (float)(VD * L);
        const float mean = sum * invN;
        const float var = ssq * invN - mean * mean;
        s_mean = mean;
        s_sd = sqrtf(var + EPS);
    }
    __syncthreads();
    g_Bc[b][g][c] = s_mean * g_S1[g][c] + (0.5f * g_e2[c] - g_S2[g][c]) * s_sd;
}

// ---------------- K3: dots = X @ M^T, argmax, gather codes -----------------
// R9 structure; As row stride 68 (16B aligned) so the warp-uniform token
// reads become 2 x LDS.128 broadcast per k (was 8 scalar LDS) -> crossbar
// drops below the fma floor.
__global__ __launch_bounds__(256, 2) void k3_vq(const float* __restrict__ x,
                                                const float* __restrict__ emb,
                                                float* __restrict__ out) {
    const int b = blockIdx.z, g = blockIdx.y, l0 = blockIdx.x * 64;
    const int tid = threadIdx.x, w = tid >> 5, lane = tid & 31;

    __shared__ __align__(16) float Ms[2][16][NC];   // 2 x 20 KB
    __shared__ __align__(16) float As[2][16][68];   // stride 68: 16B-aligned rows

    const float* xrow = x + ((size_t)(b * L + l0)) * DIM + g * VD;
    const float* Mg = &g_MT[g][0][0];

    const int la = tid >> 2;            // token this thread loads (0..63)
    const int qa = tid & 3;             // k-quad

    unsigned long long acc[8][5];
#pragma unroll
    for (int i = 0; i < 8; ++i)
#pragma unroll
        for (int j = 0; j < 5; ++j) acc[i][j] = 0ull;

    // prologue: chunk 0
#pragma unroll
    for (int n = 0; n < 5; ++n) {
        const int idx = tid + n * 256;
        const int r = idx / 80, col = (idx % 80) * 4;
        cp_async16(smem_u32(&Ms[0][r][col]), Mg + (size_t)r * NC + col);
    }
    cp_commit();
    {
        const float4 v = *(const float4*)(xrow + (size_t)la * DIM + qa * 4);
        As[0][qa * 4 + 0][la] = v.x; As[0][qa * 4 + 1][la] = v.y;
        As[0][qa * 4 + 2][la] = v.z; As[0][qa * 4 + 3][la] = v.w;
    }
    cp_wait0();
    __syncthreads();

    int s = 0;
    for (int step = 0; step < 16; ++step) {
        float4 an;
        if (step < 15) {
            const int kb = (step + 1) * 16;
#pragma unroll
            for (int n = 0; n < 5; ++n) {
                const int idx = tid + n * 256;
                const int r = idx / 80, col = (idx % 80) * 4;
                cp_async16(smem_u32(&Ms[s ^ 1][r][col]),
                           Mg + (size_t)(kb + r) * NC + col);
            }
            cp_commit();
            an = *(const float4*)(xrow + (size_t)la * DIM + kb + qa * 4);
        }
#pragma unroll
        for (int k = 0; k < 16; ++k) {
            unsigned long long m[5];
#pragma unroll
            for (int j = 0; j < 5; ++j)
                m[j] = *(const unsigned long long*)&Ms[s][k][j * 64 + lane * 2];
            // warp-uniform token values: two LDS.128 broadcasts
            const float4 t0 = *(const float4*)&As[s][k][w * 8];
            const float4 t1 = *(const float4*)&As[s][k][w * 8 + 4];
            const float tv[8] = { t0.x, t0.y, t0.z, t0.w, t1.x, t1.y, t1.z, t1.w };
#pragma unroll
            for (int i = 0; i < 8; ++i) {
                const unsigned long long ad = pk2(tv[i], tv[i]);
#pragma unroll
                for (int j = 0; j < 5; ++j) acc[i][j] = ffma2(ad, m[j], acc[i][j]);
            }
        }
        if (step < 15) {
            const int d = s ^ 1;
            As[d][qa * 4 + 0][la] = an.x; As[d][qa * 4 + 1][la] = an.y;
            As[d][qa * 4 + 2][la] = an.z; As[d][qa * 4 + 3][la] = an.w;
        }
        cp_wait0();
        __syncthreads();
        s ^= 1;
    }

    // bias + argmax (tie-break: lowest code index)
    float2 bc[5];
#pragma unroll
    for (int j = 0; j < 5; ++j)
        bc[j] = *(const float2*)&g_Bc[b][g][j * 64 + lane * 2];

    const unsigned FULL = 0xffffffffu;
    int bestc[8];
#pragma unroll
    for (int i = 0; i < 8; ++i) {
        float bv = -1e30f; int bi = 0x7fffffff;
#pragma unroll
        for (int j = 0; j < 5; ++j) {
            float lo, hi; upk2(acc[i][j], lo, hi);
            const int c0 = j * 64 + lane * 2;
            const float s0 = lo - bc[j].x;
            const float s1 = hi - bc[j].y;
            if (s0 > bv || (s0 == bv && c0 < bi)) { bv = s0; bi = c0; }
            if (s1 > bv || (s1 == bv && (c0 + 1) < bi)) { bv = s1; bi = c0 + 1; }
        }
#pragma unroll
        for (int off = 16; off; off >>= 1) {
            const float ov = __shfl_xor_sync(FULL, bv, off);
            const int oc = __shfl_xor_sync(FULL, bi, off);
            if (ov > bv || (ov == bv && oc < bi)) { bv = ov; bi = oc; }
        }
        bestc[i] = bi;
    }

    // gather: out[b, l, g*VD : (g+1)*VD] = emb[bestc]
    float* orow = out + ((size_t)(b * L + l0 + w * 8)) * DIM + g * VD;
#pragma unroll
    for (int i = 0; i < 8; ++i) {
        const float4* src = (const float4*)(emb + (size_t)bestc[i] * VD);
        float4* dst = (float4*)(orow + (size_t)i * DIM);
        dst[lane] = src[lane];
        dst[lane + 32] = src[lane + 32];
    }
}

// ---------------- launch ---------------------------------------------------
extern "C" void kernel_launch(void* const* d_in, const int* in_sizes, int n_in,
                              void* d_out, int out_size) {
    (void)in_sizes; (void)n_in; (void)out_size;
    const float* x   = (const float*)d_in[0];
    const float* W   = (const float*)d_in[1];
    const float* gw  = (const float*)d_in[2];
    const float* gb  = (const float*)d_in[3];
    const float* emb = (const float*)d_in[4];
    float* out = (float*)d_out;

    k0_prep<<<dim3(NC / 8, G), 256>>>(W, gw, gb, emb);
    k1_stats<<<dim3(2, 16, 32), 256>>>(x, W);
    k2_finalize<<<dim3(BS, G), NC>>>();
    k3_vq<<<dim3(L / 64, G, BS), 256>>>(x, emb, out);
}